// round 9
// baseline (speedup 1.0000x reference)
#include <cuda_runtime.h>
#include <cuda_fp16.h>
#include <math.h>
#include <stdint.h>

#define NTOK 2048
#define BB   8
#define EE   256
#define HH   512
#define NB   (NTOK*BB)

// ---------------------------------------------------------------------------
// Static device scratch (sanctioned no-alloc workaround)
// ---------------------------------------------------------------------------
__device__ float  g_invnorm[NB];
__device__ float  g_denom[NB];
__device__ double g_sumsq;
__device__ __half g_xh[(size_t)NB * EE];               // x normalized, fp16, (N,B,E)
__device__ __half g_hh[(size_t)NB * HH];               // h fp16, (N,B,H)
__device__ __half g_P[(size_t)BB * NTOK * NTOK];       // exp(scores), fp16, [b][i][j]

// ---------------------------------------------------------------------------
// PTX helpers (base-target only: ldmatrix / mma.sync / cp.async — no tcgen05!)
// ---------------------------------------------------------------------------
__device__ __forceinline__ uint32_t smem_u32(const void* p) {
    uint32_t a;
    asm("{ .reg .u64 t; cvta.to.shared.u64 t, %1; cvt.u32.u64 %0, t; }" : "=r"(a) : "l"(p));
    return a;
}
__device__ __forceinline__ void cp16(uint32_t dst, const void* src) {
    asm volatile("cp.async.cg.shared.global [%0], [%1], 16;" :: "r"(dst), "l"(src));
}
#define CP_COMMIT() asm volatile("cp.async.commit_group;")
#define CP_WAIT1()  asm volatile("cp.async.wait_group 1;")
#define CP_WAIT0()  asm volatile("cp.async.wait_group 0;")

__device__ __forceinline__ void ldm4(uint32_t* r, uint32_t a) {
    asm volatile("ldmatrix.sync.aligned.m8n8.x4.shared.b16 {%0,%1,%2,%3}, [%4];"
                 : "=r"(r[0]), "=r"(r[1]), "=r"(r[2]), "=r"(r[3]) : "r"(a));
}
__device__ __forceinline__ void ldm4t(uint32_t* r, uint32_t a) {
    asm volatile("ldmatrix.sync.aligned.m8n8.x4.trans.shared.b16 {%0,%1,%2,%3}, [%4];"
                 : "=r"(r[0]), "=r"(r[1]), "=r"(r[2]), "=r"(r[3]) : "r"(a));
}
__device__ __forceinline__ void mma16816(float* c, const uint32_t* a, const uint32_t* b) {
    asm volatile(
        "mma.sync.aligned.m16n8k16.row.col.f32.f16.f16.f32 "
        "{%0,%1,%2,%3}, {%4,%5,%6,%7}, {%8,%9}, {%0,%1,%2,%3};"
        : "+f"(c[0]), "+f"(c[1]), "+f"(c[2]), "+f"(c[3])
        : "r"(a[0]), "r"(a[1]), "r"(a[2]), "r"(a[3]), "r"(b[0]), "r"(b[1]));
}

// smem strides (bytes). Chosen conflict-free for ldmatrix lane patterns and
// 16B-aligned for cp.async: 80B for [row][32k] tiles, 272B for [32k][128n].
#define STRIDE_RK 80
#define STRIDE_KN 272

// ---------------------------------------------------------------------------
// K0: zero accumulators (graph replays re-run everything)
// ---------------------------------------------------------------------------
__global__ void k_zero() {
    int i = blockIdx.x * blockDim.x + threadIdx.x;
    if (i < NB) g_denom[i] = 0.0f;
    if (i == 0) g_sumsq = 0.0;
}

// ---------------------------------------------------------------------------
// K1: inverse L2 norms of x rows
// ---------------------------------------------------------------------------
__global__ void k_norm(const float* __restrict__ x) {
    int warp = (blockIdx.x * blockDim.x + threadIdx.x) >> 5;
    int lane = threadIdx.x & 31;
    if (warp >= NB) return;
    const float4* row = (const float4*)(x + (size_t)warp * EE);
    float s = 0.f;
#pragma unroll
    for (int i = 0; i < EE / 128; ++i) {
        float4 v = row[lane + i * 32];
        s += v.x * v.x + v.y * v.y + v.z * v.z + v.w * v.w;
    }
#pragma unroll
    for (int o = 16; o; o >>= 1) s += __shfl_down_sync(0xffffffffu, s, o);
    if (lane == 0) g_invnorm[warp] = rsqrtf(s);
}

// ---------------------------------------------------------------------------
// K2a: x -> x̂ fp16 (normalization folded into the conversion)
// ---------------------------------------------------------------------------
__global__ void k_cvt_x(const float* __restrict__ x) {
    int i = blockIdx.x * blockDim.x + threadIdx.x;       // over NB*EE/4
    if (i >= NB * EE / 4) return;
    float4 v = ((const float4*)x)[i];
    float inv = g_invnorm[i >> 6];                        // EE/4 = 64 float4 per row
    __half2* dst = (__half2*)g_xh + (size_t)i * 2;
    dst[0] = __floats2half2_rn(v.x * inv, v.y * inv);
    dst[1] = __floats2half2_rn(v.z * inv, v.w * inv);
}

// ---------------------------------------------------------------------------
// K2b: h -> fp16
// ---------------------------------------------------------------------------
__global__ void k_cvt_h(const float* __restrict__ h) {
    int i = blockIdx.x * blockDim.x + threadIdx.x;       // over NB*HH/4
    if (i >= NB * HH / 4) return;
    float4 v = ((const float4*)h)[i];
    __half2* dst = (__half2*)g_hh + (size_t)i * 2;
    dst[0] = __floats2half2_rn(v.x, v.y);
    dst[1] = __floats2half2_rn(v.z, v.w);
}

// ---------------------------------------------------------------------------
// K3: P = exp(x̂ x̂ᵀ) via fp16 mma.sync. CTA tile 128x128, BK=32, 8 warps
// (2m x 4n), warp tile 64x32. A smem [m][k] str 80B, B smem [n][k] str 80B.
// Epilogue: exp -> g_P (fp16) + row-sum atomics into g_denom.
// ---------------------------------------------------------------------------
__global__ void __launch_bounds__(256) k_scores(int _unused) {
    extern __shared__ char dsm[];
    uint32_t S = smem_u32(dsm);
    const uint32_t Ab[2] = {S, S + 10240};
    const uint32_t Bb[2] = {S + 20480, S + 30720};

    const int b  = blockIdx.z;
    const int i0 = blockIdx.x * 128;
    const int j0 = blockIdx.y * 128;
    const int tid = threadIdx.x, lane = tid & 31, wid = tid >> 5;
    const int wm = wid >> 2, wn = wid & 3;

    float cfr[4][4][4];
#pragma unroll
    for (int mt = 0; mt < 4; ++mt)
#pragma unroll
        for (int nt = 0; nt < 4; ++nt)
#pragma unroll
            for (int q = 0; q < 4; ++q) cfr[mt][nt][q] = 0.f;

    auto load = [&](int c) {
        int s = c & 1, k0 = c * 32;
#pragma unroll
        for (int it = 0; it < 2; ++it) {
            int idx = tid + it * 256, r = idx >> 2, q = idx & 3;
            cp16(Ab[s] + r * STRIDE_RK + q * 16,
                 g_xh + ((size_t)(i0 + r) * BB + b) * EE + k0 + q * 8);
            cp16(Bb[s] + r * STRIDE_RK + q * 16,
                 g_xh + ((size_t)(j0 + r) * BB + b) * EE + k0 + q * 8);
        }
        CP_COMMIT();
    };
    auto compute = [&](int c) {
        int s = c & 1;
#pragma unroll
        for (int ks = 0; ks < 2; ++ks) {
            uint32_t af[4][4], bf[4][2];
#pragma unroll
            for (int mt = 0; mt < 4; ++mt)
                ldm4(af[mt], Ab[s] + (wm * 64 + mt * 16 + (lane & 15)) * STRIDE_RK
                             + (ks * 16 + ((lane >> 4) << 3)) * 2);
            int g = lane >> 3;
#pragma unroll
            for (int np = 0; np < 2; ++np) {
                uint32_t r[4];
                ldm4(r, Bb[s] + (wn * 32 + (np * 2 + (g >> 1)) * 8 + (lane & 7)) * STRIDE_RK
                        + (ks * 16 + (g & 1) * 8) * 2);
                bf[np * 2][0] = r[0]; bf[np * 2][1] = r[1];
                bf[np * 2 + 1][0] = r[2]; bf[np * 2 + 1][1] = r[3];
            }
#pragma unroll
            for (int mt = 0; mt < 4; ++mt)
#pragma unroll
                for (int nt = 0; nt < 4; ++nt)
                    mma16816(cfr[mt][nt], af[mt], bf[nt]);
        }
    };

    const int NCH = EE / 32;   // 8
    load(0); load(1);
    for (int c = 0; c < NCH; ++c) {
        if (c + 1 < NCH) CP_WAIT1(); else CP_WAIT0();
        __syncthreads();
        compute(c);
        __syncthreads();
        if (c + 2 < NCH) load(c + 2);
    }

    // epilogue: exp, fp16 store, row-sum atomics
    float rsum[8];
#pragma unroll
    for (int i = 0; i < 8; ++i) rsum[i] = 0.f;
#pragma unroll
    for (int mt = 0; mt < 4; ++mt) {
        int row0 = i0 + wm * 64 + mt * 16 + (lane >> 2);
#pragma unroll
        for (int nt = 0; nt < 4; ++nt) {
            float p0 = __expf(cfr[mt][nt][0]), p1 = __expf(cfr[mt][nt][1]);
            float p2 = __expf(cfr[mt][nt][2]), p3 = __expf(cfr[mt][nt][3]);
            int col = j0 + wn * 32 + nt * 8 + 2 * (lane & 3);
            *(__half2*)(g_P + ((size_t)b * NTOK + row0) * NTOK + col)     = __floats2half2_rn(p0, p1);
            *(__half2*)(g_P + ((size_t)b * NTOK + row0 + 8) * NTOK + col) = __floats2half2_rn(p2, p3);
            rsum[mt * 2]     += p0 + p1;
            rsum[mt * 2 + 1] += p2 + p3;
        }
    }
#pragma unroll
    for (int i = 0; i < 8; ++i) {
        float v = rsum[i];
        v += __shfl_xor_sync(0xffffffffu, v, 1);
        v += __shfl_xor_sync(0xffffffffu, v, 2);
        if ((lane & 3) == 0) {
            int row = i0 + wm * 64 + (i >> 1) * 16 + (i & 1) * 8 + (lane >> 2);
            atomicAdd(&g_denom[row * BB + b], v);
        }
    }
}

// ---------------------------------------------------------------------------
// K4: out = (P @ h) / denom via fp16 mma.sync. CTA tile 128x128(h-cols),
// K = 2048, BK=32. A smem [m][k] str 80B; B smem [k][n] str 272B (ldmatrix.trans).
// Epilogue: /denom, fp32 store, global sum-of-squares.
// ---------------------------------------------------------------------------
__global__ void __launch_bounds__(256) k_out(float* __restrict__ out) {
    extern __shared__ char dsm[];
    __shared__ float red[8];
    uint32_t S = smem_u32(dsm);
    const uint32_t Ab[2] = {S, S + 10240};
    const uint32_t Bb[2] = {S + 20480, S + 20480 + 8704};

    const int b  = blockIdx.z;
    const int i0 = blockIdx.x * 128;
    const int h0 = blockIdx.y * 128;
    const int tid = threadIdx.x, lane = tid & 31, wid = tid >> 5;
    const int wm = wid >> 2, wn = wid & 3;

    float cfr[4][4][4];
#pragma unroll
    for (int mt = 0; mt < 4; ++mt)
#pragma unroll
        for (int nt = 0; nt < 4; ++nt)
#pragma unroll
            for (int q = 0; q < 4; ++q) cfr[mt][nt][q] = 0.f;

    auto load = [&](int c) {
        int s = c & 1, k0 = c * 32;
#pragma unroll
        for (int it = 0; it < 2; ++it) {
            int idx = tid + it * 256;
            {   // A: 128 rows x 64B from P
                int r = idx >> 2, q = idx & 3;
                cp16(Ab[s] + r * STRIDE_RK + q * 16,
                     g_P + ((size_t)b * NTOK + i0 + r) * NTOK + k0 + q * 8);
            }
            {   // B: 32 rows (tokens) x 256B from hh
                int r = idx >> 4, q = idx & 15;
                cp16(Bb[s] + r * STRIDE_KN + q * 16,
                     g_hh + ((size_t)(k0 + r) * BB + b) * HH + h0 + q * 8);
            }
        }
        CP_COMMIT();
    };
    auto compute = [&](int c) {
        int s = c & 1;
#pragma unroll
        for (int ks = 0; ks < 2; ++ks) {
            uint32_t af[4][4], bf[4][2];
#pragma unroll
            for (int mt = 0; mt < 4; ++mt)
                ldm4(af[mt], Ab[s] + (wm * 64 + mt * 16 + (lane & 15)) * STRIDE_RK
                             + (ks * 16 + ((lane >> 4) << 3)) * 2);
            int g = lane >> 3;
#pragma unroll
            for (int np = 0; np < 2; ++np) {
                uint32_t r[4];
                ldm4t(r, Bb[s] + (ks * 16 + (g & 1) * 8 + (lane & 7)) * STRIDE_KN
                         + (wn * 32 + (np * 2 + (g >> 1)) * 8) * 2);
                bf[np * 2][0] = r[0]; bf[np * 2][1] = r[1];
                bf[np * 2 + 1][0] = r[2]; bf[np * 2 + 1][1] = r[3];
            }
#pragma unroll
            for (int mt = 0; mt < 4; ++mt)
#pragma unroll
                for (int nt = 0; nt < 4; ++nt)
                    mma16816(cfr[mt][nt], af[mt], bf[nt]);
        }
    };

    const int NCH = NTOK / 32;   // 64
    load(0); load(1);
    for (int c = 0; c < NCH; ++c) {
        if (c + 1 < NCH) CP_WAIT1(); else CP_WAIT0();
        __syncthreads();
        compute(c);
        __syncthreads();
        if (c + 2 < NCH) load(c + 2);
    }

    // epilogue: divide by denom, store fp32, accumulate global sum of squares
    float lss = 0.f;
#pragma unroll
    for (int mt = 0; mt < 4; ++mt) {
        int row0 = i0 + wm * 64 + mt * 16 + (lane >> 2);
        float inv0 = 1.0f / g_denom[row0 * BB + b];
        float inv1 = 1.0f / g_denom[(row0 + 8) * BB + b];
#pragma unroll
        for (int nt = 0; nt < 4; ++nt) {
            int col = h0 + wn * 32 + nt * 8 + 2 * (lane & 3);
            float v0 = cfr[mt][nt][0] * inv0, v1 = cfr[mt][nt][1] * inv0;
            float v2 = cfr[mt][nt][2] * inv1, v3 = cfr[mt][nt][3] * inv1;
            *(float2*)(out + ((size_t)row0 * BB + b) * HH + col)       = make_float2(v0, v1);
            *(float2*)(out + ((size_t)(row0 + 8) * BB + b) * HH + col) = make_float2(v2, v3);
            lss += v0 * v0 + v1 * v1 + v2 * v2 + v3 * v3;
        }
    }
#pragma unroll
    for (int o = 16; o; o >>= 1) lss += __shfl_xor_sync(0xffffffffu, lss, o);
    if (lane == 0) red[wid] = lss;
    __syncthreads();
    if (tid == 0) {
        float s = 0.f;
#pragma unroll
        for (int i = 0; i < 8; ++i) s += red[i];
        atomicAdd(&g_sumsq, (double)s);
    }
}

// ---------------------------------------------------------------------------
// K5: scale by 1/||g||_F
// ---------------------------------------------------------------------------
__global__ void k_scale(float* __restrict__ out) {
    float s = (float)(1.0 / sqrt(g_sumsq));
    long long total  = (long long)NTOK * BB * HH;
    long long stride = (long long)gridDim.x * blockDim.x;
    for (long long i = blockIdx.x * (long long)blockDim.x + threadIdx.x; i < total; i += stride)
        out[i] *= s;
}

// ---------------------------------------------------------------------------
extern "C" void kernel_launch(void* const* d_in, const int* in_sizes, int n_in,
                              void* d_out, int out_size) {
    const float* x;
    const float* h;
    if (in_sizes[0] == NTOK * BB * EE) {
        x = (const float*)d_in[0];
        h = (const float*)d_in[1];
    } else {
        x = (const float*)d_in[1];
        h = (const float*)d_in[0];
    }
    float* out = (float*)d_out;

    const int SMEM1 = 40960;   // k_scores: 2x(10240 A) + 2x(10240 B)
    const int SMEM2 = 37888;   // k_out:    2x(10240 A) + 2x(8704 B)

    k_zero<<<(NB + 255) / 256, 256>>>();
    k_norm<<<NB / 8, 256>>>(x);
    k_cvt_x<<<(NB * EE / 4 + 255) / 256, 256>>>(x);
    k_cvt_h<<<(NB * HH / 4 + 255) / 256, 256>>>(h);
    k_scores<<<dim3(NTOK / 128, NTOK / 128, BB), 256, SMEM1>>>(0);
    k_out<<<dim3(NTOK / 128, HH / 128, BB), 256, SMEM2>>>(out);
    k_scale<<<2048, 256>>>(out);
}

// round 10
// speedup vs baseline: 1.0063x; 1.0063x over previous
#include <cuda_runtime.h>
#include <cuda_fp16.h>
#include <math.h>
#include <stdint.h>

#define NTOK 2048
#define BB   8
#define EE   256
#define HH   512
#define NB   (NTOK*BB)

// ---------------------------------------------------------------------------
// Static device scratch (sanctioned no-alloc workaround)
// ---------------------------------------------------------------------------
__device__ float  g_invnorm[NB];
__device__ float  g_denom[NB];
__device__ double g_sumsq;
__device__ __half g_xh[(size_t)NB * EE];               // x normalized, fp16, (N,B,E)
__device__ __half g_hh[(size_t)NB * HH];               // h fp16, (N,B,H)
__device__ __half g_P[(size_t)BB * NTOK * NTOK];       // exp(scores), fp16, [b][i][j]

// ---------------------------------------------------------------------------
// PTX helpers (base-target only: ldmatrix / mma.sync / cp.async — no tcgen05!)
// ---------------------------------------------------------------------------
__device__ __forceinline__ uint32_t smem_u32(const void* p) {
    uint32_t a;
    asm("{ .reg .u64 t; cvta.to.shared.u64 t, %1; cvt.u32.u64 %0, t; }" : "=r"(a) : "l"(p));
    return a;
}
__device__ __forceinline__ void cp16(uint32_t dst, const void* src) {
    asm volatile("cp.async.cg.shared.global [%0], [%1], 16;" :: "r"(dst), "l"(src));
}
#define CP_COMMIT() asm volatile("cp.async.commit_group;")
#define CP_WAIT1()  asm volatile("cp.async.wait_group 1;")
#define CP_WAIT0()  asm volatile("cp.async.wait_group 0;")

__device__ __forceinline__ void ldm4(uint32_t* r, uint32_t a) {
    asm volatile("ldmatrix.sync.aligned.m8n8.x4.shared.b16 {%0,%1,%2,%3}, [%4];"
                 : "=r"(r[0]), "=r"(r[1]), "=r"(r[2]), "=r"(r[3]) : "r"(a));
}
__device__ __forceinline__ void ldm4t(uint32_t* r, uint32_t a) {
    asm volatile("ldmatrix.sync.aligned.m8n8.x4.trans.shared.b16 {%0,%1,%2,%3}, [%4];"
                 : "=r"(r[0]), "=r"(r[1]), "=r"(r[2]), "=r"(r[3]) : "r"(a));
}
__device__ __forceinline__ void mma16816(float* c, const uint32_t* a, const uint32_t* b) {
    asm volatile(
        "mma.sync.aligned.m16n8k16.row.col.f32.f16.f16.f32 "
        "{%0,%1,%2,%3}, {%4,%5,%6,%7}, {%8,%9}, {%0,%1,%2,%3};"
        : "+f"(c[0]), "+f"(c[1]), "+f"(c[2]), "+f"(c[3])
        : "r"(a[0]), "r"(a[1]), "r"(a[2]), "r"(a[3]), "r"(b[0]), "r"(b[1]));
}

// smem strides (bytes). Chosen conflict-free for ldmatrix lane patterns and
// 16B-aligned for cp.async: 80B for [row][32k] tiles, 272B for [32k][128n].
#define STRIDE_RK 80
#define STRIDE_KN 272

// ---------------------------------------------------------------------------
// K0: zero accumulators (graph replays re-run everything)
// ---------------------------------------------------------------------------
__global__ void k_zero() {
    int i = blockIdx.x * blockDim.x + threadIdx.x;
    if (i < NB) g_denom[i] = 0.0f;
    if (i == 0) g_sumsq = 0.0;
}

// ---------------------------------------------------------------------------
// K1: inverse L2 norms of x rows
// ---------------------------------------------------------------------------
__global__ void k_norm(const float* __restrict__ x) {
    int warp = (blockIdx.x * blockDim.x + threadIdx.x) >> 5;
    int lane = threadIdx.x & 31;
    if (warp >= NB) return;
    const float4* row = (const float4*)(x + (size_t)warp * EE);
    float s = 0.f;
#pragma unroll
    for (int i = 0; i < EE / 128; ++i) {
        float4 v = row[lane + i * 32];
        s += v.x * v.x + v.y * v.y + v.z * v.z + v.w * v.w;
    }
#pragma unroll
    for (int o = 16; o; o >>= 1) s += __shfl_down_sync(0xffffffffu, s, o);
    if (lane == 0) g_invnorm[warp] = rsqrtf(s);
}

// ---------------------------------------------------------------------------
// K2a: x -> x̂ fp16 (normalization folded into the conversion)
// ---------------------------------------------------------------------------
__global__ void k_cvt_x(const float* __restrict__ x) {
    int i = blockIdx.x * blockDim.x + threadIdx.x;       // over NB*EE/4
    if (i >= NB * EE / 4) return;
    float4 v = ((const float4*)x)[i];
    float inv = g_invnorm[i >> 6];                        // EE/4 = 64 float4 per row
    __half2* dst = (__half2*)g_xh + (size_t)i * 2;
    dst[0] = __floats2half2_rn(v.x * inv, v.y * inv);
    dst[1] = __floats2half2_rn(v.z * inv, v.w * inv);
}

// ---------------------------------------------------------------------------
// K2b: h -> fp16
// ---------------------------------------------------------------------------
__global__ void k_cvt_h(const float* __restrict__ h) {
    int i = blockIdx.x * blockDim.x + threadIdx.x;       // over NB*HH/4
    if (i >= NB * HH / 4) return;
    float4 v = ((const float4*)h)[i];
    __half2* dst = (__half2*)g_hh + (size_t)i * 2;
    dst[0] = __floats2half2_rn(v.x, v.y);
    dst[1] = __floats2half2_rn(v.z, v.w);
}

// ---------------------------------------------------------------------------
// K3: P = exp(x̂ x̂ᵀ) via fp16 mma.sync. CTA tile 128x128, BK=32, 8 warps
// (2m x 4n), warp tile 64x32. A smem [m][k] str 80B, B smem [n][k] str 80B.
// Epilogue: exp -> g_P (fp16) + row-sum atomics into g_denom.
// ---------------------------------------------------------------------------
__global__ void __launch_bounds__(256) k_scores(int _unused) {
    extern __shared__ char dsm[];
    uint32_t S = smem_u32(dsm);
    const uint32_t Ab[2] = {S, S + 10240};
    const uint32_t Bb[2] = {S + 20480, S + 30720};

    const int b  = blockIdx.z;
    const int i0 = blockIdx.x * 128;
    const int j0 = blockIdx.y * 128;
    const int tid = threadIdx.x, lane = tid & 31, wid = tid >> 5;
    const int wm = wid >> 2, wn = wid & 3;

    float cfr[4][4][4];
#pragma unroll
    for (int mt = 0; mt < 4; ++mt)
#pragma unroll
        for (int nt = 0; nt < 4; ++nt)
#pragma unroll
            for (int q = 0; q < 4; ++q) cfr[mt][nt][q] = 0.f;

    auto load = [&](int c) {
        int s = c & 1, k0 = c * 32;
#pragma unroll
        for (int it = 0; it < 2; ++it) {
            int idx = tid + it * 256, r = idx >> 2, q = idx & 3;
            cp16(Ab[s] + r * STRIDE_RK + q * 16,
                 g_xh + ((size_t)(i0 + r) * BB + b) * EE + k0 + q * 8);
            cp16(Bb[s] + r * STRIDE_RK + q * 16,
                 g_xh + ((size_t)(j0 + r) * BB + b) * EE + k0 + q * 8);
        }
        CP_COMMIT();
    };
    auto compute = [&](int c) {
        int s = c & 1;
#pragma unroll
        for (int ks = 0; ks < 2; ++ks) {
            uint32_t af[4][4], bf[4][2];
#pragma unroll
            for (int mt = 0; mt < 4; ++mt)
                ldm4(af[mt], Ab[s] + (wm * 64 + mt * 16 + (lane & 15)) * STRIDE_RK
                             + (ks * 16 + ((lane >> 4) << 3)) * 2);
            int g = lane >> 3;
#pragma unroll
            for (int np = 0; np < 2; ++np) {
                uint32_t r[4];
                ldm4(r, Bb[s] + (wn * 32 + (np * 2 + (g >> 1)) * 8 + (lane & 7)) * STRIDE_RK
                        + (ks * 16 + (g & 1) * 8) * 2);
                bf[np * 2][0] = r[0]; bf[np * 2][1] = r[1];
                bf[np * 2 + 1][0] = r[2]; bf[np * 2 + 1][1] = r[3];
            }
#pragma unroll
            for (int mt = 0; mt < 4; ++mt)
#pragma unroll
                for (int nt = 0; nt < 4; ++nt)
                    mma16816(cfr[mt][nt], af[mt], bf[nt]);
        }
    };

    const int NCH = EE / 32;   // 8
    load(0); load(1);
    for (int c = 0; c < NCH; ++c) {
        if (c + 1 < NCH) CP_WAIT1(); else CP_WAIT0();
        __syncthreads();
        compute(c);
        __syncthreads();
        if (c + 2 < NCH) load(c + 2);
    }

    // epilogue: exp, fp16 store, row-sum atomics
    float rsum[8];
#pragma unroll
    for (int i = 0; i < 8; ++i) rsum[i] = 0.f;
#pragma unroll
    for (int mt = 0; mt < 4; ++mt) {
        int row0 = i0 + wm * 64 + mt * 16 + (lane >> 2);
#pragma unroll
        for (int nt = 0; nt < 4; ++nt) {
            float p0 = __expf(cfr[mt][nt][0]), p1 = __expf(cfr[mt][nt][1]);
            float p2 = __expf(cfr[mt][nt][2]), p3 = __expf(cfr[mt][nt][3]);
            int col = j0 + wn * 32 + nt * 8 + 2 * (lane & 3);
            *(__half2*)(g_P + ((size_t)b * NTOK + row0) * NTOK + col)     = __floats2half2_rn(p0, p1);
            *(__half2*)(g_P + ((size_t)b * NTOK + row0 + 8) * NTOK + col) = __floats2half2_rn(p2, p3);
            rsum[mt * 2]     += p0 + p1;
            rsum[mt * 2 + 1] += p2 + p3;
        }
    }
#pragma unroll
    for (int i = 0; i < 8; ++i) {
        float v = rsum[i];
        v += __shfl_xor_sync(0xffffffffu, v, 1);
        v += __shfl_xor_sync(0xffffffffu, v, 2);
        if ((lane & 3) == 0) {
            int row = i0 + wm * 64 + (i >> 1) * 16 + (i & 1) * 8 + (lane >> 2);
            atomicAdd(&g_denom[row * BB + b], v);
        }
    }
}

// ---------------------------------------------------------------------------
// K4: out = (P @ h) / denom via fp16 mma.sync. CTA tile 128x128(h-cols),
// K = 2048, BK=32. A smem [m][k] str 80B; B smem [k][n] str 272B (ldmatrix.trans).
// Epilogue: /denom, fp32 store, global sum-of-squares.
// ---------------------------------------------------------------------------
__global__ void __launch_bounds__(256) k_out(float* __restrict__ out) {
    extern __shared__ char dsm[];
    __shared__ float red[8];
    uint32_t S = smem_u32(dsm);
    const uint32_t Ab[2] = {S, S + 10240};
    const uint32_t Bb[2] = {S + 20480, S + 20480 + 8704};

    const int b  = blockIdx.z;
    const int i0 = blockIdx.x * 128;
    const int h0 = blockIdx.y * 128;
    const int tid = threadIdx.x, lane = tid & 31, wid = tid >> 5;
    const int wm = wid >> 2, wn = wid & 3;

    float cfr[4][4][4];
#pragma unroll
    for (int mt = 0; mt < 4; ++mt)
#pragma unroll
        for (int nt = 0; nt < 4; ++nt)
#pragma unroll
            for (int q = 0; q < 4; ++q) cfr[mt][nt][q] = 0.f;

    auto load = [&](int c) {
        int s = c & 1, k0 = c * 32;
#pragma unroll
        for (int it = 0; it < 2; ++it) {
            int idx = tid + it * 256;
            {   // A: 128 rows x 64B from P
                int r = idx >> 2, q = idx & 3;
                cp16(Ab[s] + r * STRIDE_RK + q * 16,
                     g_P + ((size_t)b * NTOK + i0 + r) * NTOK + k0 + q * 8);
            }
            {   // B: 32 rows (tokens) x 256B from hh
                int r = idx >> 4, q = idx & 15;
                cp16(Bb[s] + r * STRIDE_KN + q * 16,
                     g_hh + ((size_t)(k0 + r) * BB + b) * HH + h0 + q * 8);
            }
        }
        CP_COMMIT();
    };
    auto compute = [&](int c) {
        int s = c & 1;
#pragma unroll
        for (int ks = 0; ks < 2; ++ks) {
            uint32_t af[4][4], bf[4][2];
#pragma unroll
            for (int mt = 0; mt < 4; ++mt)
                ldm4(af[mt], Ab[s] + (wm * 64 + mt * 16 + (lane & 15)) * STRIDE_RK
                             + (ks * 16 + ((lane >> 4) << 3)) * 2);
            int g = lane >> 3;
#pragma unroll
            for (int np = 0; np < 2; ++np) {
                uint32_t r[4];
                ldm4t(r, Bb[s] + (ks * 16 + (g & 1) * 8 + (lane & 7)) * STRIDE_KN
                         + (wn * 32 + (np * 2 + (g >> 1)) * 8) * 2);
                bf[np * 2][0] = r[0]; bf[np * 2][1] = r[1];
                bf[np * 2 + 1][0] = r[2]; bf[np * 2 + 1][1] = r[3];
            }
#pragma unroll
            for (int mt = 0; mt < 4; ++mt)
#pragma unroll
                for (int nt = 0; nt < 4; ++nt)
                    mma16816(cfr[mt][nt], af[mt], bf[nt]);
        }
    };

    const int NCH = NTOK / 32;   // 64
    load(0); load(1);
    for (int c = 0; c < NCH; ++c) {
        if (c + 1 < NCH) CP_WAIT1(); else CP_WAIT0();
        __syncthreads();
        compute(c);
        __syncthreads();
        if (c + 2 < NCH) load(c + 2);
    }

    // epilogue: divide by denom, store fp32, accumulate global sum of squares
    float lss = 0.f;
#pragma unroll
    for (int mt = 0; mt < 4; ++mt) {
        int row0 = i0 + wm * 64 + mt * 16 + (lane >> 2);
        float inv0 = 1.0f / g_denom[row0 * BB + b];
        float inv1 = 1.0f / g_denom[(row0 + 8) * BB + b];
#pragma unroll
        for (int nt = 0; nt < 4; ++nt) {
            int col = h0 + wn * 32 + nt * 8 + 2 * (lane & 3);
            float v0 = cfr[mt][nt][0] * inv0, v1 = cfr[mt][nt][1] * inv0;
            float v2 = cfr[mt][nt][2] * inv1, v3 = cfr[mt][nt][3] * inv1;
            *(float2*)(out + ((size_t)row0 * BB + b) * HH + col)       = make_float2(v0, v1);
            *(float2*)(out + ((size_t)(row0 + 8) * BB + b) * HH + col) = make_float2(v2, v3);
            lss += v0 * v0 + v1 * v1 + v2 * v2 + v3 * v3;
        }
    }
#pragma unroll
    for (int o = 16; o; o >>= 1) lss += __shfl_xor_sync(0xffffffffu, lss, o);
    if (lane == 0) red[wid] = lss;
    __syncthreads();
    if (tid == 0) {
        float s = 0.f;
#pragma unroll
        for (int i = 0; i < 8; ++i) s += red[i];
        atomicAdd(&g_sumsq, (double)s);
    }
}

// ---------------------------------------------------------------------------
// K5: scale by 1/||g||_F
// ---------------------------------------------------------------------------
__global__ void k_scale(float* __restrict__ out) {
    float s = (float)(1.0 / sqrt(g_sumsq));
    long long total  = (long long)NTOK * BB * HH;
    long long stride = (long long)gridDim.x * blockDim.x;
    for (long long i = blockIdx.x * (long long)blockDim.x + threadIdx.x; i < total; i += stride)
        out[i] *= s;
}

// ---------------------------------------------------------------------------
extern "C" void kernel_launch(void* const* d_in, const int* in_sizes, int n_in,
                              void* d_out, int out_size) {
    const float* x;
    const float* h;
    if (in_sizes[0] == NTOK * BB * EE) {
        x = (const float*)d_in[0];
        h = (const float*)d_in[1];
    } else {
        x = (const float*)d_in[1];
        h = (const float*)d_in[0];
    }
    float* out = (float*)d_out;

    const int SMEM1 = 40960;   // k_scores: 2x(10240 A) + 2x(10240 B)
    const int SMEM2 = 37888;   // k_out:    2x(10240 A) + 2x(8704 B)

    k_zero<<<(NB + 255) / 256, 256>>>();
    k_norm<<<NB / 8, 256>>>(x);
    k_cvt_x<<<(NB * EE / 4 + 255) / 256, 256>>>(x);
    k_cvt_h<<<(NB * HH / 4 + 255) / 256, 256>>>(h);
    k_scores<<<dim3(NTOK / 128, NTOK / 128, BB), 256, SMEM1>>>(0);
    k_out<<<dim3(NTOK / 128, HH / 128, BB), 256, SMEM2>>>(out);
    k_scale<<<2048, 256>>>(out);
}